// round 1
// baseline (speedup 1.0000x reference)
#include <cuda_runtime.h>
#include <math.h>

// Problem constants (fixed-shape problem)
#define NFEAT 16
#define EFEAT 8
#define HC    256     // H*C
#define NCLS  4

static const int MAXN = 50000;
static const int MAXE = 800000;

// ---------------- scratch (device globals; no allocation allowed) ----------
__device__ float g_x1  [MAXN * 64];
__device__ float g_q   [MAXN * HC];
__device__ float g_k   [MAXN * HC];
__device__ float g_v   [MAXN * HC];
__device__ float g_skip[MAXN * HC];
__device__ float g_g   [MAXN * HC];   // g[n, h*64+i] = sum_c wedge[i, h*64+c] * q[n, h*64+c]
__device__ float g_qb  [MAXN * 4];    // q . bedge per head
__device__ float g_e   [MAXE * 64];   // edge MLP output, stored in dst-sorted order
__device__ float g_outv[MAXN * HC];   // sum a*v[src]
__device__ float g_t   [MAXN * HC];   // sum a*e  (t[n, h*64+i] laid out as channel u*32+lane)
__device__ float g_suma[MAXN * 4];
__device__ float g_act [MAXN * HC];
__device__ int   g_deg [MAXN];
__device__ int   g_rowptr[MAXN + 1];
__device__ int   g_cursor[MAXN];
__device__ int   g_eid [MAXE];        // original edge id at sorted position
__device__ int   g_src [MAXE];        // src node at sorted position

// ---------------- CSR build ----------------
__global__ void k_zero_deg(int n) {
    int i = blockIdx.x * blockDim.x + threadIdx.x;
    if (i < n) g_deg[i] = 0;
}

__global__ void k_hist(const int* __restrict__ ei, int e) {
    int i = blockIdx.x * blockDim.x + threadIdx.x;
    if (i < e) atomicAdd(&g_deg[ei[e + i]], 1);   // dst row
}

// single-block exclusive scan over deg -> rowptr, cursor
__global__ void k_scan(int n) {
    __shared__ int sh[1024];
    __shared__ int s_off;
    int tid = threadIdx.x;
    if (tid == 0) { s_off = 0; g_rowptr[0] = 0; }
    __syncthreads();
    for (int base = 0; base < n; base += 1024) {
        int i = base + tid;
        int val = (i < n) ? g_deg[i] : 0;
        sh[tid] = val;
        __syncthreads();
        for (int off = 1; off < 1024; off <<= 1) {
            int y = (tid >= off) ? sh[tid - off] : 0;
            __syncthreads();
            sh[tid] += y;
            __syncthreads();
        }
        int incl = sh[tid];
        if (i < n) {
            g_rowptr[i + 1] = s_off + incl;
            g_cursor[i]     = s_off + incl - val;
        }
        __syncthreads();
        if (tid == 0) s_off += sh[1023];
        __syncthreads();
    }
}

__global__ void k_scatter(const int* __restrict__ ei, int e) {
    int i = blockIdx.x * blockDim.x + threadIdx.x;
    if (i < e) {
        int dst = ei[e + i];
        int pos = atomicAdd(&g_cursor[dst], 1);
        g_eid[pos] = i;
        g_src[pos] = ei[i];
    }
}

// ---------------- node embed: x1 = relu(x @ w00 + b00) ----------------
__global__ void k_node_embed(const float* __restrict__ x,
                             const float* __restrict__ w00,
                             const float* __restrict__ b00, int n) {
    __shared__ float ws[NFEAT * 64];
    __shared__ float xs[64][NFEAT];
    int tid = threadIdx.x;
    for (int i = tid; i < NFEAT * 64; i += 256) ws[i] = w00[i];
    int nb = blockIdx.x * 64;
    for (int i = tid; i < 64 * NFEAT; i += 256) {
        int nn = nb + i / NFEAT;
        xs[i / NFEAT][i % NFEAT] = (nn < n) ? x[nn * NFEAT + (i % NFEAT)] : 0.f;
    }
    __syncthreads();
    int ln = tid >> 2;
    int node = nb + ln;
    int c0 = (tid & 3) * 16;
    if (node < n) {
        #pragma unroll
        for (int j = 0; j < 16; j++) {
            float acc = __ldg(&b00[c0 + j]);
            #pragma unroll
            for (int i = 0; i < NFEAT; i++) acc += xs[ln][i] * ws[i * 64 + c0 + j];
            g_x1[node * 64 + c0 + j] = fmaxf(acc, 0.f);
        }
    }
}

// ---------------- projections: y = x1 @ W + b  (64 -> 256) ----------------
__global__ void k_proj(const float* __restrict__ W, const float* __restrict__ b,
                       int sel, int n) {
    __shared__ float xs[32][64];
    int tid = threadIdx.x;
    int nb = blockIdx.x * 32;
    for (int i = tid; i < 32 * 64; i += 256) {
        int nn = nb + i / 64;
        xs[i / 64][i % 64] = (nn < n) ? g_x1[nn * 64 + (i % 64)] : 0.f;
    }
    __syncthreads();
    float acc[32];
    float bb = __ldg(&b[tid]);
    #pragma unroll
    for (int m = 0; m < 32; m++) acc[m] = bb;
    for (int i = 0; i < 64; i++) {
        float w = __ldg(&W[i * HC + tid]);
        #pragma unroll
        for (int m = 0; m < 32; m++) acc[m] += xs[m][i] * w;
    }
    float* out = (sel == 0) ? g_q : (sel == 1) ? g_k : (sel == 2) ? g_v : g_skip;
    #pragma unroll
    for (int m = 0; m < 32; m++) {
        int nn = nb + m;
        if (nn < n) out[nn * HC + tid] = acc[m];
    }
}

// ---------------- g = per-head wedge^T applied to q; qb = q . bedge --------
__global__ void k_g(const float* __restrict__ wedge, const float* __restrict__ bedge,
                    int n) {
    __shared__ float qs[32][HC];
    int tid = threadIdx.x;
    int nb = blockIdx.x * 32;
    for (int i = tid; i < 32 * HC; i += 256) {
        int nn = nb + i / HC;
        qs[i / HC][i % HC] = (nn < n) ? g_q[nn * HC + (i % HC)] : 0.f;
    }
    __syncthreads();
    int h = tid >> 6, ii = tid & 63;
    float acc[32];
    #pragma unroll
    for (int m = 0; m < 32; m++) acc[m] = 0.f;
    for (int c = 0; c < 64; c++) {
        float w = __ldg(&wedge[ii * HC + h * 64 + c]);
        #pragma unroll
        for (int m = 0; m < 32; m++) acc[m] += qs[m][h * 64 + c] * w;
    }
    #pragma unroll
    for (int m = 0; m < 32; m++) {
        int nn = nb + m;
        if (nn < n) g_g[nn * HC + tid] = acc[m];
    }
    if (tid < 128) {
        int m = tid >> 2, h2 = tid & 3;
        int nn = nb + m;
        if (nn < n) {
            float s = 0.f;
            for (int c = 0; c < 64; c++) s += qs[m][h2 * 64 + c] * __ldg(&bedge[h2 * 64 + c]);
            g_qb[nn * 4 + h2] = s;
        }
    }
}

// ---------------- edge MLP (3 layers, 8->64->64->64), dst-sorted output ----
__global__ void k_edgemlp(const float* __restrict__ eattr,
                          const float* __restrict__ we1, const float* __restrict__ be1,
                          const float* __restrict__ we2, const float* __restrict__ be2,
                          const float* __restrict__ we3, const float* __restrict__ be3,
                          int e) {
    __shared__ float w2s[64 * 64];
    __shared__ float w3s[64 * 64];
    __shared__ float h1[32][64];
    __shared__ float h2[32][64];
    int tid = threadIdx.x;
    for (int i = tid; i < 4096; i += 256) { w2s[i] = we2[i]; w3s[i] = we3[i]; }
    int pb = blockIdx.x * 32;
    int j = tid & 63, er = tid >> 6;   // 4 edge-rows per r-step

    // layer 1
    #pragma unroll
    for (int r = 0; r < 8; r++) {
        int ee = er + r * 4;
        int p = pb + ee;
        float acc = __ldg(&be1[j]);
        if (p < e) {
            int eid = g_eid[p];
            #pragma unroll
            for (int i = 0; i < EFEAT; i++)
                acc += __ldg(&eattr[eid * EFEAT + i]) * __ldg(&we1[i * 64 + j]);
        }
        h1[ee][j] = fmaxf(acc, 0.f);
    }
    __syncthreads();

    // layer 2 (register-blocked over edge rows)
    {
        float acc[8];
        float bb = __ldg(&be2[j]);
        #pragma unroll
        for (int r = 0; r < 8; r++) acc[r] = bb;
        for (int i = 0; i < 64; i++) {
            float w = w2s[i * 64 + j];
            #pragma unroll
            for (int r = 0; r < 8; r++) acc[r] += h1[er + r * 4][i] * w;
        }
        __syncthreads();
        #pragma unroll
        for (int r = 0; r < 8; r++) h2[er + r * 4][j] = fmaxf(acc[r], 0.f);
    }
    __syncthreads();

    // layer 3
    {
        float acc[8];
        float bb = __ldg(&be3[j]);
        #pragma unroll
        for (int r = 0; r < 8; r++) acc[r] = bb;
        for (int i = 0; i < 64; i++) {
            float w = w3s[i * 64 + j];
            #pragma unroll
            for (int r = 0; r < 8; r++) acc[r] += h2[er + r * 4][i] * w;
        }
        #pragma unroll
        for (int r = 0; r < 8; r++) {
            int ee = er + r * 4;
            int p = pb + ee;
            if (p < e) g_e[p * 64 + j] = fmaxf(acc[r], 0.f);
        }
    }
}

// ---------------- attention: one warp per dst node -------------------------
__global__ void k_attn(int n) {
    int gw = (blockIdx.x * blockDim.x + threadIdx.x) >> 5;
    int lane = threadIdx.x & 31;
    if (gw >= n) return;
    int node = gw;
    int beg = g_rowptr[node], end = g_rowptr[node + 1];

    float qr[8], gr[8];
    #pragma unroll
    for (int u = 0; u < 8; u++) {
        qr[u] = g_q[node * HC + u * 32 + lane];
        gr[u] = g_g[node * HC + u * 32 + lane];
    }
    float qb0[4];
    #pragma unroll
    for (int h = 0; h < 4; h++) qb0[h] = g_qb[node * 4 + h];

    float s[4] = {0.f, 0.f, 0.f, 0.f};
    float accv[8], acct[8];
    #pragma unroll
    for (int u = 0; u < 8; u++) { accv[u] = 0.f; acct[u] = 0.f; }

    for (int p = beg; p < end; p++) {
        int src = g_src[p];
        float elo = g_e[p * 64 + lane];
        float ehi = g_e[p * 64 + 32 + lane];
        float kv[8];
        #pragma unroll
        for (int u = 0; u < 8; u++) kv[u] = g_k[src * HC + u * 32 + lane];
        float ph[4];
        #pragma unroll
        for (int h = 0; h < 4; h++)
            ph[h] = qr[2*h] * kv[2*h] + qr[2*h+1] * kv[2*h+1]
                  + gr[2*h] * elo     + gr[2*h+1] * ehi;
        #pragma unroll
        for (int off = 16; off; off >>= 1) {
            #pragma unroll
            for (int h = 0; h < 4; h++)
                ph[h] += __shfl_xor_sync(0xffffffffu, ph[h], off);
        }
        float pe[4];
        #pragma unroll
        for (int h = 0; h < 4; h++) {
            pe[h] = expf((ph[h] + qb0[h]) * 0.125f);
            s[h] += pe[h];
        }
        #pragma unroll
        for (int u = 0; u < 8; u++) {
            float vv = g_v[src * HC + u * 32 + lane];
            accv[u] += pe[u >> 1] * vv;
            acct[u] += pe[u >> 1] * ((u & 1) ? ehi : elo);
        }
    }

    float sinv[4], sa[4];
    #pragma unroll
    for (int h = 0; h < 4; h++) {
        sinv[h] = 1.f / (s[h] + 1e-16f);
        sa[h]   = s[h] * sinv[h];
    }
    #pragma unroll
    for (int u = 0; u < 8; u++) {
        g_outv[node * HC + u * 32 + lane] = accv[u] * sinv[u >> 1];
        g_t   [node * HC + u * 32 + lane] = acct[u] * sinv[u >> 1];
    }
    if (lane < 4) g_suma[node * 4 + lane] = sa[lane];
}

// ---------------- epilogue 1: out = outv + suma*bedge + t@wedge + skip; LN; relu
__global__ void k_post(const float* __restrict__ wedge, const float* __restrict__ bedge,
                       const float* __restrict__ ln_g, const float* __restrict__ ln_b,
                       int n) {
    __shared__ float ts[16][HC];
    __shared__ float os[16][HC];
    int tid = threadIdx.x;
    int nb = blockIdx.x * 16;
    for (int i = tid; i < 16 * HC; i += 256) {
        int nn = nb + i / HC;
        ts[i / HC][i % HC] = (nn < n) ? g_t[nn * HC + (i % HC)] : 0.f;
    }
    __syncthreads();
    int h = tid >> 6;
    float acc[16];
    #pragma unroll
    for (int m = 0; m < 16; m++) acc[m] = 0.f;
    for (int i = 0; i < 64; i++) {
        float w = __ldg(&wedge[i * HC + tid]);
        #pragma unroll
        for (int m = 0; m < 16; m++) acc[m] += ts[m][h * 64 + i] * w;
    }
    float be = __ldg(&bedge[tid]);
    #pragma unroll
    for (int m = 0; m < 16; m++) {
        int nn = nb + m;
        if (nn < n) {
            float val = g_outv[nn * HC + tid] + g_suma[nn * 4 + h] * be
                      + g_skip[nn * HC + tid] + acc[m];
            os[m][tid] = val;
        }
    }
    __syncthreads();
    int wid = tid >> 5, lane = tid & 31;
    for (int m = wid; m < 16; m += 8) {
        int nn = nb + m;
        if (nn >= n) continue;
        float sum = 0.f, sq = 0.f;
        #pragma unroll
        for (int u = 0; u < 8; u++) {
            float v = os[m][u * 32 + lane];
            sum += v; sq += v * v;
        }
        #pragma unroll
        for (int off = 16; off; off >>= 1) {
            sum += __shfl_xor_sync(0xffffffffu, sum, off);
            sq  += __shfl_xor_sync(0xffffffffu, sq,  off);
        }
        float mu = sum * (1.f / 256.f);
        float var = sq * (1.f / 256.f) - mu * mu;
        float rs = rsqrtf(var + 1e-5f);
        #pragma unroll
        for (int u = 0; u < 8; u++) {
            int j = u * 32 + lane;
            float v = (os[m][j] - mu) * rs * __ldg(&ln_g[j]) + __ldg(&ln_b[j]);
            g_act[nn * HC + j] = fmaxf(v, 0.f);
        }
    }
}

// ---------------- epilogue 2: head MLP + log_softmax -----------------------
__global__ void k_head(const float* __restrict__ w1, const float* __restrict__ b1,
                       const float* __restrict__ w2, const float* __restrict__ b2,
                       float* __restrict__ out, int n) {
    __shared__ float as[16][HC];
    __shared__ float hs[16][128];
    __shared__ float ls[16][NCLS];
    int tid = threadIdx.x;   // 128 threads
    int nb = blockIdx.x * 16;
    for (int i = tid; i < 16 * HC; i += 128) {
        int nn = nb + i / HC;
        as[i / HC][i % HC] = (nn < n) ? g_act[nn * HC + (i % HC)] : 0.f;
    }
    __syncthreads();
    float acc[16];
    float bb = __ldg(&b1[tid]);
    #pragma unroll
    for (int m = 0; m < 16; m++) acc[m] = bb;
    for (int i = 0; i < HC; i++) {
        float w = __ldg(&w1[i * 128 + tid]);
        #pragma unroll
        for (int m = 0; m < 16; m++) acc[m] += as[m][i] * w;
    }
    #pragma unroll
    for (int m = 0; m < 16; m++) hs[m][tid] = fmaxf(acc[m], 0.f);
    __syncthreads();
    if (tid < 64) {
        int m = tid >> 2, c = tid & 3;
        float a = __ldg(&b2[c]);
        for (int i = 0; i < 128; i++) a += hs[m][i] * __ldg(&w2[i * NCLS + c]);
        ls[m][c] = a;
    }
    __syncthreads();
    if (tid < 16) {
        int nn = nb + tid;
        if (nn < n) {
            float l0 = ls[tid][0], l1 = ls[tid][1], l2 = ls[tid][2], l3 = ls[tid][3];
            float mx = fmaxf(fmaxf(l0, l1), fmaxf(l2, l3));
            float se = expf(l0 - mx) + expf(l1 - mx) + expf(l2 - mx) + expf(l3 - mx);
            float lse = mx + logf(se);
            out[nn * NCLS + 0] = l0 - lse;
            out[nn * NCLS + 1] = l1 - lse;
            out[nn * NCLS + 2] = l2 - lse;
            out[nn * NCLS + 3] = l3 - lse;
        }
    }
}

// ---------------- launcher ----------------
extern "C" void kernel_launch(void* const* d_in, const int* in_sizes, int n_in,
                              void* d_out, int out_size) {
    const float* x     = (const float*)d_in[0];
    const int*   ei    = (const int*)  d_in[1];
    const float* eattr = (const float*)d_in[2];
    const float* w00   = (const float*)d_in[3];
    const float* b00   = (const float*)d_in[4];
    const float* we1   = (const float*)d_in[5];
    const float* be1   = (const float*)d_in[6];
    const float* we2   = (const float*)d_in[7];
    const float* be2   = (const float*)d_in[8];
    const float* we3   = (const float*)d_in[9];
    const float* be3   = (const float*)d_in[10];
    const float* wq    = (const float*)d_in[11];
    const float* bq    = (const float*)d_in[12];
    const float* wk    = (const float*)d_in[13];
    const float* bk    = (const float*)d_in[14];
    const float* wv    = (const float*)d_in[15];
    const float* bv    = (const float*)d_in[16];
    const float* wedge = (const float*)d_in[17];
    const float* bedge = (const float*)d_in[18];
    const float* wskip = (const float*)d_in[19];
    const float* bskip = (const float*)d_in[20];
    const float* ln_g  = (const float*)d_in[21];
    const float* ln_b  = (const float*)d_in[22];
    const float* w1    = (const float*)d_in[23];
    const float* b1    = (const float*)d_in[24];
    const float* w2    = (const float*)d_in[25];
    const float* b2    = (const float*)d_in[26];
    float* out = (float*)d_out;

    int n = in_sizes[0] / NFEAT;
    int e = in_sizes[1] / 2;

    // CSR build
    k_zero_deg<<<(n + 255) / 256, 256>>>(n);
    k_hist<<<(e + 255) / 256, 256>>>(ei, e);
    k_scan<<<1, 1024>>>(n);
    k_scatter<<<(e + 255) / 256, 256>>>(ei, e);

    // node pipeline
    k_node_embed<<<(n + 63) / 64, 256>>>(x, w00, b00, n);
    k_proj<<<(n + 31) / 32, 256>>>(wq, bq, 0, n);
    k_proj<<<(n + 31) / 32, 256>>>(wk, bk, 1, n);
    k_proj<<<(n + 31) / 32, 256>>>(wv, bv, 2, n);
    k_proj<<<(n + 31) / 32, 256>>>(wskip, bskip, 3, n);
    k_g<<<(n + 31) / 32, 256>>>(wedge, bedge, n);

    // edge pipeline
    k_edgemlp<<<(e + 31) / 32, 256>>>(eattr, we1, be1, we2, be2, we3, be3, e);

    // attention
    k_attn<<<(n + 7) / 8, 256>>>(n);

    // epilogues
    k_post<<<(n + 15) / 16, 256>>>(wedge, bedge, ln_g, ln_b, n);
    k_head<<<(n + 15) / 16, 128>>>(w1, b1, w2, b2, out, n);
}

// round 2
// speedup vs baseline: 1.0778x; 1.0778x over previous
#include <cuda_runtime.h>
#include <math.h>

#define NFEAT 16
#define EFEAT 8
#define HC    256
#define NCLS  4

static const int MAXN = 50000;
static const int MAXE = 800000;

// ---------------- scratch ----------------
__device__ float g_x1  [MAXN * 64];
__device__ float g_q   [MAXN * HC];
__device__ float g_k   [MAXN * HC];
__device__ float g_v   [MAXN * HC];
__device__ float g_skip[MAXN * HC];
__device__ float g_g   [MAXN * HC];
__device__ float g_qb  [MAXN * 4];
__device__ float g_e   [MAXE * 64];
__device__ float g_outv[MAXN * HC];
__device__ float g_t   [MAXN * HC];
__device__ float g_suma[MAXN * 4];
__device__ float g_act [MAXN * HC];
__device__ int   g_deg [MAXN];
__device__ int   g_rowptr[MAXN + 1];
__device__ int   g_cursor[MAXN];
__device__ int   g_eid [MAXE];
__device__ int   g_src [MAXE];

// ---------------- CSR build ----------------
__global__ void k_zero_deg(int n) {
    int i = blockIdx.x * blockDim.x + threadIdx.x;
    if (i < n) g_deg[i] = 0;
}

__global__ void k_hist(const int* __restrict__ ei, int e) {
    int i = blockIdx.x * blockDim.x + threadIdx.x;
    if (i < e) atomicAdd(&g_deg[ei[e + i]], 1);
}

__global__ void k_scan(int n) {
    __shared__ int sh[1024];
    __shared__ int s_off;
    int tid = threadIdx.x;
    if (tid == 0) { s_off = 0; g_rowptr[0] = 0; }
    __syncthreads();
    for (int base = 0; base < n; base += 1024) {
        int i = base + tid;
        int val = (i < n) ? g_deg[i] : 0;
        sh[tid] = val;
        __syncthreads();
        for (int off = 1; off < 1024; off <<= 1) {
            int y = (tid >= off) ? sh[tid - off] : 0;
            __syncthreads();
            sh[tid] += y;
            __syncthreads();
        }
        int incl = sh[tid];
        if (i < n) {
            g_rowptr[i + 1] = s_off + incl;
            g_cursor[i]     = s_off + incl - val;
        }
        __syncthreads();
        if (tid == 0) s_off += sh[1023];
        __syncthreads();
    }
}

__global__ void k_scatter(const int* __restrict__ ei, int e) {
    int i = blockIdx.x * blockDim.x + threadIdx.x;
    if (i < e) {
        int dst = ei[e + i];
        int pos = atomicAdd(&g_cursor[dst], 1);
        g_eid[pos] = i;
        g_src[pos] = ei[i];
    }
}

// ---------------- node embed ----------------
__global__ void k_node_embed(const float* __restrict__ x,
                             const float* __restrict__ w00,
                             const float* __restrict__ b00, int n) {
    __shared__ float ws[NFEAT * 64];
    __shared__ float xs[64][NFEAT];
    int tid = threadIdx.x;
    for (int i = tid; i < NFEAT * 64; i += 256) ws[i] = w00[i];
    int nb = blockIdx.x * 64;
    for (int i = tid; i < 64 * NFEAT; i += 256) {
        int nn = nb + i / NFEAT;
        xs[i / NFEAT][i % NFEAT] = (nn < n) ? x[nn * NFEAT + (i % NFEAT)] : 0.f;
    }
    __syncthreads();
    int ln = tid >> 2;
    int node = nb + ln;
    int c0 = (tid & 3) * 16;
    if (node < n) {
        #pragma unroll
        for (int j = 0; j < 16; j++) {
            float acc = __ldg(&b00[c0 + j]);
            #pragma unroll
            for (int i = 0; i < NFEAT; i++) acc += xs[ln][i] * ws[i * 64 + c0 + j];
            g_x1[node * 64 + c0 + j] = fmaxf(acc, 0.f);
        }
    }
}

// ---------------- projections (64 -> 256) ----------------
__global__ void k_proj(const float* __restrict__ W, const float* __restrict__ b,
                       int sel, int n) {
    __shared__ float xs[32][64];
    int tid = threadIdx.x;
    int nb = blockIdx.x * 32;
    for (int i = tid; i < 32 * 64; i += 256) {
        int nn = nb + i / 64;
        xs[i / 64][i % 64] = (nn < n) ? g_x1[nn * 64 + (i % 64)] : 0.f;
    }
    __syncthreads();
    float acc[32];
    float bb = __ldg(&b[tid]);
    #pragma unroll
    for (int m = 0; m < 32; m++) acc[m] = bb;
    for (int i = 0; i < 64; i++) {
        float w = __ldg(&W[i * HC + tid]);
        #pragma unroll
        for (int m = 0; m < 32; m++) acc[m] += xs[m][i] * w;
    }
    float* out = (sel == 0) ? g_q : (sel == 1) ? g_k : (sel == 2) ? g_v : g_skip;
    #pragma unroll
    for (int m = 0; m < 32; m++) {
        int nn = nb + m;
        if (nn < n) out[nn * HC + tid] = acc[m];
    }
}

// ---------------- g / qb precompute ----------------
__global__ void k_g(const float* __restrict__ wedge, const float* __restrict__ bedge,
                    int n) {
    __shared__ float qs[32][HC];
    int tid = threadIdx.x;
    int nb = blockIdx.x * 32;
    for (int i = tid; i < 32 * HC; i += 256) {
        int nn = nb + i / HC;
        qs[i / HC][i % HC] = (nn < n) ? g_q[nn * HC + (i % HC)] : 0.f;
    }
    __syncthreads();
    int h = tid >> 6, ii = tid & 63;
    float acc[32];
    #pragma unroll
    for (int m = 0; m < 32; m++) acc[m] = 0.f;
    for (int c = 0; c < 64; c++) {
        float w = __ldg(&wedge[ii * HC + h * 64 + c]);
        #pragma unroll
        for (int m = 0; m < 32; m++) acc[m] += qs[m][h * 64 + c] * w;
    }
    #pragma unroll
    for (int m = 0; m < 32; m++) {
        int nn = nb + m;
        if (nn < n) g_g[nn * HC + tid] = acc[m];
    }
    if (tid < 128) {
        int m = tid >> 2, h2 = tid & 3;
        int nn = nb + m;
        if (nn < n) {
            float s = 0.f;
            for (int c = 0; c < 64; c++) s += qs[m][h2 * 64 + c] * __ldg(&bedge[h2 * 64 + c]);
            g_qb[nn * 4 + h2] = s;
        }
    }
}

// ---------------- edge MLP (vectorized, transposed weights) ----------------
__global__ void k_edgemlp(const float* __restrict__ eattr,
                          const float* __restrict__ we1, const float* __restrict__ be1,
                          const float* __restrict__ we2, const float* __restrict__ be2,
                          const float* __restrict__ we3, const float* __restrict__ be3,
                          int e) {
    __shared__ float w2t[64 * 68];   // [j][i], padded rows (68 floats) for LDS.128
    __shared__ float w3t[64 * 68];
    __shared__ float w1s[8 * 64];
    __shared__ float es[32][8];
    __shared__ float h1[32 * 64];
    __shared__ float h2[32 * 64];
    int tid = threadIdx.x;
    for (int i = tid; i < 4096; i += 256) {
        int r = i >> 6, c = i & 63;
        w2t[c * 68 + r] = we2[i];
        w3t[c * 68 + r] = we3[i];
    }
    for (int i = tid; i < 512; i += 256) w1s[i] = we1[i];
    int pb = blockIdx.x * 32;
    {
        int row = tid >> 3, c = tid & 7;
        int p = pb + row;
        float v = 0.f;
        if (p < e) {
            int eid = g_eid[p];
            v = __ldg(&eattr[eid * EFEAT + c]);
        }
        es[row][c] = v;
    }
    __syncthreads();

    int j = tid & 63, er = tid >> 6;

    // layer 1 (8 -> 64)
    float bb1 = __ldg(&be1[j]);
    #pragma unroll
    for (int r = 0; r < 8; r++) {
        int row = er + r * 4;
        float acc = bb1;
        #pragma unroll
        for (int i = 0; i < 8; i++) acc += es[row][i] * w1s[i * 64 + j];
        h1[row * 64 + j] = fmaxf(acc, 0.f);
    }
    __syncthreads();

    // layer 2 (64 -> 64)
    {
        float acc[8];
        float bb = __ldg(&be2[j]);
        #pragma unroll
        for (int r = 0; r < 8; r++) acc[r] = bb;
        const float4* wr = (const float4*)&w2t[j * 68];
        #pragma unroll
        for (int i4 = 0; i4 < 16; i4++) {
            float4 w = wr[i4];
            #pragma unroll
            for (int r = 0; r < 8; r++) {
                float4 hv = *(const float4*)&h1[(er + r * 4) * 64 + i4 * 4];
                acc[r] += hv.x * w.x + hv.y * w.y + hv.z * w.z + hv.w * w.w;
            }
        }
        #pragma unroll
        for (int r = 0; r < 8; r++) h2[(er + r * 4) * 64 + j] = fmaxf(acc[r], 0.f);
    }
    __syncthreads();

    // layer 3 (64 -> 64) -> g_e
    {
        float acc[8];
        float bb = __ldg(&be3[j]);
        #pragma unroll
        for (int r = 0; r < 8; r++) acc[r] = bb;
        const float4* wr = (const float4*)&w3t[j * 68];
        #pragma unroll
        for (int i4 = 0; i4 < 16; i4++) {
            float4 w = wr[i4];
            #pragma unroll
            for (int r = 0; r < 8; r++) {
                float4 hv = *(const float4*)&h2[(er + r * 4) * 64 + i4 * 4];
                acc[r] += hv.x * w.x + hv.y * w.y + hv.z * w.z + hv.w * w.w;
            }
        }
        #pragma unroll
        for (int r = 0; r < 8; r++) {
            int ee = er + r * 4;
            int p = pb + ee;
            if (p < e) g_e[p * 64 + j] = fmaxf(acc[r], 0.f);
        }
    }
}

// ---------------- attention: warp per node, 8-lane head groups -------------
__device__ __forceinline__ float dot4(float4 a, float4 b) {
    return a.x * b.x + a.y * b.y + a.z * b.z + a.w * b.w;
}

__global__ void k_attn(int n) {
    int gw = (blockIdx.x * blockDim.x + threadIdx.x) >> 5;
    int lane = threadIdx.x & 31;
    if (gw >= n) return;
    int node = gw;
    int beg = g_rowptr[node], end = g_rowptr[node + 1];

    int h = lane >> 3;
    int c8 = (lane & 7) * 8;          // channel base within head (e-channel base)
    int chan = h * 64 + c8;           // absolute channel base (8 channels)

    float4 q0 = *(const float4*)&g_q[node * HC + chan];
    float4 q1 = *(const float4*)&g_q[node * HC + chan + 4];
    float4 gg0 = *(const float4*)&g_g[node * HC + chan];
    float4 gg1 = *(const float4*)&g_g[node * HC + chan + 4];
    float qb = g_qb[node * 4 + h];

    float s = 0.f;
    float4 av0 = {0,0,0,0}, av1 = {0,0,0,0};
    float4 at0 = {0,0,0,0}, at1 = {0,0,0,0};

    int p = beg;
    for (; p + 2 <= end; p += 2) {
        int srcA = g_src[p], srcB = g_src[p + 1];
        float4 kA0 = *(const float4*)&g_k[srcA * HC + chan];
        float4 kA1 = *(const float4*)&g_k[srcA * HC + chan + 4];
        float4 eA0 = *(const float4*)&g_e[p * 64 + c8];
        float4 eA1 = *(const float4*)&g_e[p * 64 + c8 + 4];
        float4 kB0 = *(const float4*)&g_k[srcB * HC + chan];
        float4 kB1 = *(const float4*)&g_k[srcB * HC + chan + 4];
        float4 eB0 = *(const float4*)&g_e[(p + 1) * 64 + c8];
        float4 eB1 = *(const float4*)&g_e[(p + 1) * 64 + c8 + 4];

        float dA = dot4(q0, kA0) + dot4(q1, kA1) + dot4(gg0, eA0) + dot4(gg1, eA1);
        float dB = dot4(q0, kB0) + dot4(q1, kB1) + dot4(gg0, eB0) + dot4(gg1, eB1);
        dA += __shfl_xor_sync(0xffffffffu, dA, 1);
        dB += __shfl_xor_sync(0xffffffffu, dB, 1);
        dA += __shfl_xor_sync(0xffffffffu, dA, 2);
        dB += __shfl_xor_sync(0xffffffffu, dB, 2);
        dA += __shfl_xor_sync(0xffffffffu, dA, 4);
        dB += __shfl_xor_sync(0xffffffffu, dB, 4);
        float peA = __expf((dA + qb) * 0.125f);
        float peB = __expf((dB + qb) * 0.125f);
        s += peA + peB;

        float4 vA0 = *(const float4*)&g_v[srcA * HC + chan];
        float4 vA1 = *(const float4*)&g_v[srcA * HC + chan + 4];
        float4 vB0 = *(const float4*)&g_v[srcB * HC + chan];
        float4 vB1 = *(const float4*)&g_v[srcB * HC + chan + 4];

        av0.x += peA * vA0.x + peB * vB0.x;  av0.y += peA * vA0.y + peB * vB0.y;
        av0.z += peA * vA0.z + peB * vB0.z;  av0.w += peA * vA0.w + peB * vB0.w;
        av1.x += peA * vA1.x + peB * vB1.x;  av1.y += peA * vA1.y + peB * vB1.y;
        av1.z += peA * vA1.z + peB * vB1.z;  av1.w += peA * vA1.w + peB * vB1.w;
        at0.x += peA * eA0.x + peB * eB0.x;  at0.y += peA * eA0.y + peB * eB0.y;
        at0.z += peA * eA0.z + peB * eB0.z;  at0.w += peA * eA0.w + peB * eB0.w;
        at1.x += peA * eA1.x + peB * eB1.x;  at1.y += peA * eA1.y + peB * eB1.y;
        at1.z += peA * eA1.z + peB * eB1.z;  at1.w += peA * eA1.w + peB * eB1.w;
    }
    if (p < end) {
        int src = g_src[p];
        float4 k0 = *(const float4*)&g_k[src * HC + chan];
        float4 k1 = *(const float4*)&g_k[src * HC + chan + 4];
        float4 e0 = *(const float4*)&g_e[p * 64 + c8];
        float4 e1 = *(const float4*)&g_e[p * 64 + c8 + 4];
        float d = dot4(q0, k0) + dot4(q1, k1) + dot4(gg0, e0) + dot4(gg1, e1);
        d += __shfl_xor_sync(0xffffffffu, d, 1);
        d += __shfl_xor_sync(0xffffffffu, d, 2);
        d += __shfl_xor_sync(0xffffffffu, d, 4);
        float pe = __expf((d + qb) * 0.125f);
        s += pe;
        float4 v0 = *(const float4*)&g_v[src * HC + chan];
        float4 v1 = *(const float4*)&g_v[src * HC + chan + 4];
        av0.x += pe * v0.x; av0.y += pe * v0.y; av0.z += pe * v0.z; av0.w += pe * v0.w;
        av1.x += pe * v1.x; av1.y += pe * v1.y; av1.z += pe * v1.z; av1.w += pe * v1.w;
        at0.x += pe * e0.x; at0.y += pe * e0.y; at0.z += pe * e0.z; at0.w += pe * e0.w;
        at1.x += pe * e1.x; at1.y += pe * e1.y; at1.z += pe * e1.z; at1.w += pe * e1.w;
    }

    float sinv = 1.f / (s + 1e-16f);
    float4 o0 = {av0.x * sinv, av0.y * sinv, av0.z * sinv, av0.w * sinv};
    float4 o1 = {av1.x * sinv, av1.y * sinv, av1.z * sinv, av1.w * sinv};
    float4 t0 = {at0.x * sinv, at0.y * sinv, at0.z * sinv, at0.w * sinv};
    float4 t1 = {at1.x * sinv, at1.y * sinv, at1.z * sinv, at1.w * sinv};
    *(float4*)&g_outv[node * HC + chan]     = o0;
    *(float4*)&g_outv[node * HC + chan + 4] = o1;
    *(float4*)&g_t   [node * HC + chan]     = t0;
    *(float4*)&g_t   [node * HC + chan + 4] = t1;
    if ((lane & 7) == 0) g_suma[node * 4 + h] = s * sinv;
}

// ---------------- epilogue 1 ----------------
__global__ void k_post(const float* __restrict__ wedge, const float* __restrict__ bedge,
                       const float* __restrict__ ln_g, const float* __restrict__ ln_b,
                       int n) {
    __shared__ float ts[16][HC];
    __shared__ float os[16][HC];
    int tid = threadIdx.x;
    int nb = blockIdx.x * 16;
    for (int i = tid; i < 16 * HC; i += 256) {
        int nn = nb + i / HC;
        ts[i / HC][i % HC] = (nn < n) ? g_t[nn * HC + (i % HC)] : 0.f;
    }
    __syncthreads();
    int h = tid >> 6;
    float acc[16];
    #pragma unroll
    for (int m = 0; m < 16; m++) acc[m] = 0.f;
    for (int i = 0; i < 64; i++) {
        float w = __ldg(&wedge[i * HC + tid]);
        #pragma unroll
        for (int m = 0; m < 16; m++) acc[m] += ts[m][h * 64 + i] * w;
    }
    float be = __ldg(&bedge[tid]);
    #pragma unroll
    for (int m = 0; m < 16; m++) {
        int nn = nb + m;
        if (nn < n) {
            float val = g_outv[nn * HC + tid] + g_suma[nn * 4 + h] * be
                      + g_skip[nn * HC + tid] + acc[m];
            os[m][tid] = val;
        }
    }
    __syncthreads();
    int wid = tid >> 5, lane = tid & 31;
    for (int m = wid; m < 16; m += 8) {
        int nn = nb + m;
        if (nn >= n) continue;
        float sum = 0.f, sq = 0.f;
        #pragma unroll
        for (int u = 0; u < 8; u++) {
            float v = os[m][u * 32 + lane];
            sum += v; sq += v * v;
        }
        #pragma unroll
        for (int off = 16; off; off >>= 1) {
            sum += __shfl_xor_sync(0xffffffffu, sum, off);
            sq  += __shfl_xor_sync(0xffffffffu, sq,  off);
        }
        float mu = sum * (1.f / 256.f);
        float var = sq * (1.f / 256.f) - mu * mu;
        float rs = rsqrtf(var + 1e-5f);
        #pragma unroll
        for (int u = 0; u < 8; u++) {
            int j = u * 32 + lane;
            float v = (os[m][j] - mu) * rs * __ldg(&ln_g[j]) + __ldg(&ln_b[j]);
            g_act[nn * HC + j] = fmaxf(v, 0.f);
        }
    }
}

// ---------------- epilogue 2 ----------------
__global__ void k_head(const float* __restrict__ w1, const float* __restrict__ b1,
                       const float* __restrict__ w2, const float* __restrict__ b2,
                       float* __restrict__ out, int n) {
    __shared__ float as[16][HC];
    __shared__ float hs[16][128];
    __shared__ float ls[16][NCLS];
    int tid = threadIdx.x;
    int nb = blockIdx.x * 16;
    for (int i = tid; i < 16 * HC; i += 128) {
        int nn = nb + i / HC;
        as[i / HC][i % HC] = (nn < n) ? g_act[nn * HC + (i % HC)] : 0.f;
    }
    __syncthreads();
    float acc[16];
    float bb = __ldg(&b1[tid]);
    #pragma unroll
    for (int m = 0; m < 16; m++) acc[m] = bb;
    for (int i = 0; i < HC; i++) {
        float w = __ldg(&w1[i * 128 + tid]);
        #pragma unroll
        for (int m = 0; m < 16; m++) acc[m] += as[m][i] * w;
    }
    #pragma unroll
    for (int m = 0; m < 16; m++) hs[m][tid] = fmaxf(acc[m], 0.f);
    __syncthreads();
    if (tid < 64) {
        int m = tid >> 2, c = tid & 3;
        float a = __ldg(&b2[c]);
        for (int i = 0; i < 128; i++) a += hs[m][i] * __ldg(&w2[i * NCLS + c]);
        ls[m][c] = a;
    }
    __syncthreads();
    if (tid < 16) {
        int nn = nb + tid;
        if (nn < n) {
            float l0 = ls[tid][0], l1 = ls[tid][1], l2 = ls[tid][2], l3 = ls[tid][3];
            float mx = fmaxf(fmaxf(l0, l1), fmaxf(l2, l3));
            float se = expf(l0 - mx) + expf(l1 - mx) + expf(l2 - mx) + expf(l3 - mx);
            float lse = mx + logf(se);
            out[nn * NCLS + 0] = l0 - lse;
            out[nn * NCLS + 1] = l1 - lse;
            out[nn * NCLS + 2] = l2 - lse;
            out[nn * NCLS + 3] = l3 - lse;
        }
    }
}

// ---------------- launcher ----------------
extern "C" void kernel_launch(void* const* d_in, const int* in_sizes, int n_in,
                              void* d_out, int out_size) {
    const float* x     = (const float*)d_in[0];
    const int*   ei    = (const int*)  d_in[1];
    const float* eattr = (const float*)d_in[2];
    const float* w00   = (const float*)d_in[3];
    const float* b00   = (const float*)d_in[4];
    const float* we1   = (const float*)d_in[5];
    const float* be1   = (const float*)d_in[6];
    const float* we2   = (const float*)d_in[7];
    const float* be2   = (const float*)d_in[8];
    const float* we3   = (const float*)d_in[9];
    const float* be3   = (const float*)d_in[10];
    const float* wq    = (const float*)d_in[11];
    const float* bq    = (const float*)d_in[12];
    const float* wk    = (const float*)d_in[13];
    const float* bk    = (const float*)d_in[14];
    const float* wv    = (const float*)d_in[15];
    const float* bv    = (const float*)d_in[16];
    const float* wedge = (const float*)d_in[17];
    const float* bedge = (const float*)d_in[18];
    const float* wskip = (const float*)d_in[19];
    const float* bskip = (const float*)d_in[20];
    const float* ln_g  = (const float*)d_in[21];
    const float* ln_b  = (const float*)d_in[22];
    const float* w1    = (const float*)d_in[23];
    const float* b1    = (const float*)d_in[24];
    const float* w2    = (const float*)d_in[25];
    const float* b2    = (const float*)d_in[26];
    float* out = (float*)d_out;

    int n = in_sizes[0] / NFEAT;
    int e = in_sizes[1] / 2;

    k_zero_deg<<<(n + 255) / 256, 256>>>(n);
    k_hist<<<(e + 255) / 256, 256>>>(ei, e);
    k_scan<<<1, 1024>>>(n);
    k_scatter<<<(e + 255) / 256, 256>>>(ei, e);

    k_node_embed<<<(n + 63) / 64, 256>>>(x, w00, b00, n);
    k_proj<<<(n + 31) / 32, 256>>>(wq, bq, 0, n);
    k_proj<<<(n + 31) / 32, 256>>>(wk, bk, 1, n);
    k_proj<<<(n + 31) / 32, 256>>>(wv, bv, 2, n);
    k_proj<<<(n + 31) / 32, 256>>>(wskip, bskip, 3, n);
    k_g<<<(n + 31) / 32, 256>>>(wedge, bedge, n);

    k_edgemlp<<<(e + 31) / 32, 256>>>(eattr, we1, be1, we2, be2, we3, be3, e);

    k_attn<<<(n + 7) / 8, 256>>>(n);

    k_post<<<(n + 15) / 16, 256>>>(wedge, bedge, ln_g, ln_b, n);
    k_head<<<(n + 15) / 16, 128>>>(w1, b1, w2, b2, out, n);
}